// round 2
// baseline (speedup 1.0000x reference)
#include <cuda_runtime.h>
#include <cuda_bf16.h>
#include <cstdint>

// Problem shape (fixed by the dataset)
#define MM 8192
#define NN 4096
#define KK 4096

// GEMM tiling
#define BM 128
#define BN 128
#define BK 128              // int8 elems = 128 bytes = one swizzled row
#define STAGES 3
#define NKT (KK / BK)       // 32
#define TILE_BYTES (BM * BK)             // 16384
#define STAGE_BYTES (2 * TILE_BYTES)     // 32768
#define SMEM_TOTAL (STAGES * STAGE_BYTES)

// Scratch: quantized activations + int8 weights (static device arrays are allowed)
__device__ __align__(16) int8_t g_xq[(size_t)MM * KK];
__device__ __align__(16) int8_t g_wb[(size_t)NN * KK];

__device__ __forceinline__ uint32_t s2u(const void* p) {
    return (uint32_t)__cvta_generic_to_shared(p);
}

// SW128-style swizzle: 16B-chunk index (0..7) XOR (row & 7)
__device__ __forceinline__ uint32_t tile_addr(uint32_t base, int row, int chunk) {
    return base + row * 128 + (((uint32_t)(chunk ^ (row & 7))) << 4);
}

__device__ __forceinline__ void ldsm_x4(uint32_t& r0, uint32_t& r1,
                                        uint32_t& r2, uint32_t& r3, uint32_t a) {
    asm volatile(
        "ldmatrix.sync.aligned.m8n8.x4.shared.b16 {%0,%1,%2,%3}, [%4];"
        : "=r"(r0), "=r"(r1), "=r"(r2), "=r"(r3) : "r"(a));
}

__device__ __forceinline__ void imma(int* c, uint32_t a0, uint32_t a1, uint32_t a2,
                                     uint32_t a3, uint32_t b0, uint32_t b1) {
    asm volatile(
        "mma.sync.aligned.m16n8k32.row.col.s32.s8.s8.s32 "
        "{%0,%1,%2,%3}, {%4,%5,%6,%7}, {%8,%9}, {%0,%1,%2,%3};"
        : "+r"(c[0]), "+r"(c[1]), "+r"(c[2]), "+r"(c[3])
        : "r"(a0), "r"(a1), "r"(a2), "r"(a3), "r"(b0), "r"(b1));
}

// ---------------------------------------------------------------------------
// Kernel 1: quantize activations  x -> int8(clip(round(x / s_in)))
// ---------------------------------------------------------------------------
__global__ void quant_x_kernel(const float* __restrict__ x,
                               const float* __restrict__ iscale) {
    int i = blockIdx.x * blockDim.x + threadIdx.x;
    float inv = 1.0f / iscale[0];
    float4 v = reinterpret_cast<const float4*>(x)[i];
    int a0 = (int)fminf(fmaxf(rintf(v.x * inv), -128.0f), 127.0f);
    int a1 = (int)fminf(fmaxf(rintf(v.y * inv), -128.0f), 127.0f);
    int a2 = (int)fminf(fmaxf(rintf(v.z * inv), -128.0f), 127.0f);
    int a3 = (int)fminf(fmaxf(rintf(v.w * inv), -128.0f), 127.0f);
    uint32_t p = (a0 & 0xff) | ((a1 & 0xff) << 8) | ((a2 & 0xff) << 16)
               | ((uint32_t)(a3 & 0xff) << 24);
    reinterpret_cast<uint32_t*>(g_xq)[i] = p;
}

// ---------------------------------------------------------------------------
// Kernel 2: weight int32 (int8 range) -> int8
// ---------------------------------------------------------------------------
__global__ void conv_w_kernel(const int* __restrict__ w) {
    int i = blockIdx.x * blockDim.x + threadIdx.x;
    int4 v = reinterpret_cast<const int4*>(w)[i];
    uint32_t p = (v.x & 0xff) | ((v.y & 0xff) << 8) | ((v.z & 0xff) << 16)
               | ((uint32_t)(v.w & 0xff) << 24);
    reinterpret_cast<uint32_t*>(g_wb)[i] = p;
}

// ---------------------------------------------------------------------------
// Kernel 3: int8 IMMA GEMM  out[m,n] = (sum_k A[m,k]*W[n,k]) * cs
// 128 threads = 4 warps in a 2x2 grid of 64x64 warp tiles.
// ---------------------------------------------------------------------------
__device__ __forceinline__ void load_stage(uint32_t sa, uint32_t sbw,
                                           const int8_t* ak, const int8_t* bk,
                                           int tid) {
    // 2048 16B chunks (A:1024, B:1024), 16 per thread, chunk-fastest => coalesced
#pragma unroll
    for (int i = 0; i < 16; ++i) {
        int c = i * 128 + tid;
        int row = (c >> 3) & 127;
        int ch = c & 7;
        uint32_t dst;
        const int8_t* g;
        if (c < 1024) { dst = tile_addr(sa, row, ch);  g = ak + (size_t)row * KK + ch * 16; }
        else          { dst = tile_addr(sbw, row, ch); g = bk + (size_t)row * KK + ch * 16; }
        asm volatile("cp.async.cg.shared.global [%0], [%1], 16;"
                     :: "r"(dst), "l"(g) : "memory");
    }
}

__global__ void __launch_bounds__(128, 2)
gemm_kernel(float* __restrict__ out,
            const float* __restrict__ scale, const float* __restrict__ iscale) {
    extern __shared__ char smem[];
    uint32_t sb = s2u(smem);
    int tid = threadIdx.x;
    int wid = tid >> 5, lid = tid & 31;
    int wm = wid >> 1, wn = wid & 1;          // 2x2 warps, 64x64 each

    int tm = blockIdx.x & (MM / BM - 1);      // m fast -> ktile slices stay in L2
    int tn = blockIdx.x >> 6;                 // MM/BM = 64

    const int8_t* A  = g_xq + (size_t)tm * BM * KK;
    const int8_t* Bw = g_wb + (size_t)tn * BN * KK;

    int acc[4][8][4];
#pragma unroll
    for (int i = 0; i < 4; ++i)
#pragma unroll
        for (int j = 0; j < 8; ++j)
#pragma unroll
            for (int k = 0; k < 4; ++k) acc[i][j][k] = 0;

    // prologue
#pragma unroll
    for (int s = 0; s < STAGES - 1; ++s) {
        load_stage(sb + s * STAGE_BYTES, sb + s * STAGE_BYTES + TILE_BYTES,
                   A + (size_t)s * BK, Bw + (size_t)s * BK, tid);
        asm volatile("cp.async.commit_group;" ::: "memory");
    }

    // per-lane ldmatrix row indices
    int lrow = lid & 15;           // row within 16-row block
    int lhi  = lid >> 4;           // 0: chunk 2j, 1: chunk 2j+1

    for (int kt = 0; kt < NKT; ++kt) {
        uint32_t st = sb + (kt % STAGES) * STAGE_BYTES;
        uint32_t sa = st, sbw = st + TILE_BYTES;
        asm volatile("cp.async.wait_group %0;" :: "n"(STAGES - 2) : "memory");
        __syncthreads();

#pragma unroll
        for (int j = 0; j < 4; ++j) {          // 4 k-steps of 32
            uint32_t a[4][4], b[4][4];
#pragma unroll
            for (int mt = 0; mt < 4; ++mt) {
                int row = wm * 64 + mt * 16 + lrow;
                ldsm_x4(a[mt][0], a[mt][1], a[mt][2], a[mt][3],
                        tile_addr(sa, row, 2 * j + lhi));
            }
#pragma unroll
            for (int p = 0; p < 4; ++p) {      // n16 pairs
                int row = wn * 64 + p * 16 + lrow;
                ldsm_x4(b[p][0], b[p][1], b[p][2], b[p][3],
                        tile_addr(sbw, row, 2 * j + lhi));
            }
#pragma unroll
            for (int mt = 0; mt < 4; ++mt)
#pragma unroll
                for (int p = 0; p < 4; ++p) {
                    imma(acc[mt][2 * p],     a[mt][0], a[mt][1], a[mt][2], a[mt][3],
                         b[p][0], b[p][2]);
                    imma(acc[mt][2 * p + 1], a[mt][0], a[mt][1], a[mt][2], a[mt][3],
                         b[p][1], b[p][3]);
                }
        }

        __syncthreads();
        int ktn = kt + STAGES - 1;
        if (ktn < NKT) {
            uint32_t st2 = sb + (ktn % STAGES) * STAGE_BYTES;
            load_stage(st2, st2 + TILE_BYTES,
                       A + (size_t)ktn * BK, Bw + (size_t)ktn * BK, tid);
        }
        asm volatile("cp.async.commit_group;" ::: "memory");
    }

    // epilogue: scale and store fp32
    float cs = scale[0] * iscale[0];
    int r0 = lid >> 2, c0 = (lid & 3) * 2;
#pragma unroll
    for (int mt = 0; mt < 4; ++mt) {
        size_t row0 = (size_t)tm * BM + wm * 64 + mt * 16 + r0;
#pragma unroll
        for (int nt = 0; nt < 8; ++nt) {
            size_t col = (size_t)tn * BN + wn * 64 + nt * 8 + c0;
            float2 v0, v1;
            v0.x = (float)acc[mt][nt][0] * cs;
            v0.y = (float)acc[mt][nt][1] * cs;
            v1.x = (float)acc[mt][nt][2] * cs;
            v1.y = (float)acc[mt][nt][3] * cs;
            *reinterpret_cast<float2*>(out + row0 * NN + col) = v0;
            *reinterpret_cast<float2*>(out + (row0 + 8) * NN + col) = v1;
        }
    }
}

// ---------------------------------------------------------------------------
extern "C" void kernel_launch(void* const* d_in, const int* in_sizes, int n_in,
                              void* d_out, int out_size) {
    const float* x      = (const float*)d_in[0];
    const int*   w      = (const int*)d_in[1];
    const float* scale  = (const float*)d_in[2];
    const float* iscale = (const float*)d_in[3];
    float* out = (float*)d_out;

    cudaFuncSetAttribute(gemm_kernel, cudaFuncAttributeMaxDynamicSharedMemorySize,
                         SMEM_TOTAL);

    quant_x_kernel<<<(MM * KK / 4) / 256, 256>>>(x, iscale);
    conv_w_kernel<<<(NN * KK / 4) / 256, 256>>>(w);
    gemm_kernel<<<(MM / BM) * (NN / BN), 128, SMEM_TOTAL>>>(out, scale, iscale);
}

// round 3
// speedup vs baseline: 2.4076x; 2.4076x over previous
#include <cuda_runtime.h>
#include <cuda_bf16.h>
#include <cstdint>

// Problem shape (fixed by the dataset)
#define MM 8192
#define NN 4096
#define KK 4096

// GEMM tiling (bf16 operands)
#define BM 256
#define BN 128
#define BK 64               // bf16 elems = 128 bytes = one swizzled row
#define STAGES 3
#define NKT (KK / BK)       // 64
#define A_TILE_BYTES (BM * 128)          // 32768
#define B_TILE_BYTES (BN * 128)          // 16384
#define STAGE_BYTES (A_TILE_BYTES + B_TILE_BYTES)   // 49152
#define SMEM_TOTAL (STAGES * STAGE_BYTES)           // 147456

// Scratch: quantized activations + bf16 weights (static device arrays allowed)
__device__ __align__(16) __nv_bfloat16 g_xq[(size_t)MM * KK];
__device__ __align__(16) __nv_bfloat16 g_wb[(size_t)NN * KK];

__device__ __forceinline__ uint32_t s2u(const void* p) {
    return (uint32_t)__cvta_generic_to_shared(p);
}

// XOR swizzle: 16B-chunk index (0..7) XOR (row & 7) -> conflict-free ldmatrix
__device__ __forceinline__ uint32_t tile_addr(uint32_t base, int row, int chunk) {
    return base + row * 128 + (((uint32_t)(chunk ^ (row & 7))) << 4);
}

__device__ __forceinline__ void ldsm_x4(uint32_t& r0, uint32_t& r1,
                                        uint32_t& r2, uint32_t& r3, uint32_t a) {
    asm volatile(
        "ldmatrix.sync.aligned.m8n8.x4.shared.b16 {%0,%1,%2,%3}, [%4];"
        : "=r"(r0), "=r"(r1), "=r"(r2), "=r"(r3) : "r"(a));
}

__device__ __forceinline__ void hmma(float* c, uint32_t a0, uint32_t a1, uint32_t a2,
                                     uint32_t a3, uint32_t b0, uint32_t b1) {
    asm volatile(
        "mma.sync.aligned.m16n8k16.row.col.f32.bf16.bf16.f32 "
        "{%0,%1,%2,%3}, {%4,%5,%6,%7}, {%8,%9}, {%0,%1,%2,%3};"
        : "+f"(c[0]), "+f"(c[1]), "+f"(c[2]), "+f"(c[3])
        : "r"(a0), "r"(a1), "r"(a2), "r"(a3), "r"(b0), "r"(b1));
}

// ---------------------------------------------------------------------------
// Kernel 1: quantize activations  x -> bf16(clip(round(x / s_in)))  (exact ints)
// ---------------------------------------------------------------------------
__global__ void quant_x_kernel(const float* __restrict__ x,
                               const float* __restrict__ iscale) {
    int i = blockIdx.x * blockDim.x + threadIdx.x;
    float inv = 1.0f / iscale[0];
    float4 v = reinterpret_cast<const float4*>(x)[i];
    float a0 = fminf(fmaxf(rintf(v.x * inv), -128.0f), 127.0f);
    float a1 = fminf(fmaxf(rintf(v.y * inv), -128.0f), 127.0f);
    float a2 = fminf(fmaxf(rintf(v.z * inv), -128.0f), 127.0f);
    float a3 = fminf(fmaxf(rintf(v.w * inv), -128.0f), 127.0f);
    __nv_bfloat162* o = reinterpret_cast<__nv_bfloat162*>(g_xq) + (size_t)i * 2;
    o[0] = __floats2bfloat162_rn(a0, a1);
    o[1] = __floats2bfloat162_rn(a2, a3);
}

// ---------------------------------------------------------------------------
// Kernel 2: weight int32 (int8 range) -> bf16 (exact)
// ---------------------------------------------------------------------------
__global__ void conv_w_kernel(const int* __restrict__ w) {
    int i = blockIdx.x * blockDim.x + threadIdx.x;
    int4 v = reinterpret_cast<const int4*>(w)[i];
    __nv_bfloat162* o = reinterpret_cast<__nv_bfloat162*>(g_wb) + (size_t)i * 2;
    o[0] = __floats2bfloat162_rn((float)v.x, (float)v.y);
    o[1] = __floats2bfloat162_rn((float)v.z, (float)v.w);
}

// ---------------------------------------------------------------------------
// Kernel 3: bf16 HMMA GEMM  out[m,n] = (sum_k A[m,k]*W[n,k]) * cs
// 256 threads = 8 warps in a 4x2 grid of 64x64 warp tiles.
// ---------------------------------------------------------------------------
__device__ __forceinline__ void load_stage(uint32_t sa, uint32_t sbw,
                                           const __nv_bfloat16* ak,
                                           const __nv_bfloat16* bk, int tid) {
    // 3072 16B chunks (A: 2048, B: 1024), 12 per thread, chunk-fastest coalesced
#pragma unroll
    for (int i = 0; i < 12; ++i) {
        int c = i * 256 + tid;
        int ch = c & 7;
        uint32_t dst;
        const __nv_bfloat16* g;
        if (c < 2048) {
            int row = c >> 3;
            dst = tile_addr(sa, row, ch);
            g = ak + (size_t)row * KK + ch * 8;
        } else {
            int row = (c - 2048) >> 3;
            dst = tile_addr(sbw, row, ch);
            g = bk + (size_t)row * KK + ch * 8;
        }
        asm volatile("cp.async.cg.shared.global [%0], [%1], 16;"
                     :: "r"(dst), "l"(g) : "memory");
    }
}

__global__ void __launch_bounds__(256, 1)
gemm_kernel(float* __restrict__ out,
            const float* __restrict__ scale, const float* __restrict__ iscale) {
    extern __shared__ char smem[];
    uint32_t sb = s2u(smem);
    int tid = threadIdx.x;
    int wid = tid >> 5, lid = tid & 31;
    int wm = wid >> 1, wn = wid & 1;          // 4x2 warps, 64x64 each

    int tm = blockIdx.x & (MM / BM - 1);      // m fast -> ktile slices stay in L2
    int tn = blockIdx.x >> 5;                 // MM/BM = 32

    const __nv_bfloat16* A  = g_xq + (size_t)tm * BM * KK;
    const __nv_bfloat16* Bw = g_wb + (size_t)tn * BN * KK;

    float acc[4][8][4];
#pragma unroll
    for (int i = 0; i < 4; ++i)
#pragma unroll
        for (int j = 0; j < 8; ++j)
#pragma unroll
            for (int k = 0; k < 4; ++k) acc[i][j][k] = 0.0f;

    // prologue
#pragma unroll
    for (int s = 0; s < STAGES - 1; ++s) {
        load_stage(sb + s * STAGE_BYTES, sb + s * STAGE_BYTES + A_TILE_BYTES,
                   A + (size_t)s * BK, Bw + (size_t)s * BK, tid);
        asm volatile("cp.async.commit_group;" ::: "memory");
    }

    // per-lane ldmatrix row indices
    int lrow = lid & 15;           // row within 16-row block
    int lhi  = lid >> 4;           // 0: chunk 2j, 1: chunk 2j+1

    for (int kt = 0; kt < NKT; ++kt) {
        uint32_t st = sb + (kt % STAGES) * STAGE_BYTES;
        uint32_t sa = st, sbw = st + A_TILE_BYTES;
        asm volatile("cp.async.wait_group %0;" :: "n"(STAGES - 2) : "memory");
        __syncthreads();

#pragma unroll
        for (int j = 0; j < 4; ++j) {          // 4 k-steps of 16
            uint32_t a[4][4], b[4][4];
#pragma unroll
            for (int mt = 0; mt < 4; ++mt) {
                int row = wm * 64 + mt * 16 + lrow;
                ldsm_x4(a[mt][0], a[mt][1], a[mt][2], a[mt][3],
                        tile_addr(sa, row, 2 * j + lhi));
            }
#pragma unroll
            for (int p = 0; p < 4; ++p) {      // n16 blocks
                int row = wn * 64 + p * 16 + lrow;
                ldsm_x4(b[p][0], b[p][1], b[p][2], b[p][3],
                        tile_addr(sbw, row, 2 * j + lhi));
            }
#pragma unroll
            for (int mt = 0; mt < 4; ++mt)
#pragma unroll
                for (int p = 0; p < 4; ++p) {
                    hmma(acc[mt][2 * p],     a[mt][0], a[mt][1], a[mt][2], a[mt][3],
                         b[p][0], b[p][2]);
                    hmma(acc[mt][2 * p + 1], a[mt][0], a[mt][1], a[mt][2], a[mt][3],
                         b[p][1], b[p][3]);
                }
        }

        __syncthreads();
        int ktn = kt + STAGES - 1;
        if (ktn < NKT) {
            uint32_t st2 = sb + (ktn % STAGES) * STAGE_BYTES;
            load_stage(st2, st2 + A_TILE_BYTES,
                       A + (size_t)ktn * BK, Bw + (size_t)ktn * BK, tid);
        }
        asm volatile("cp.async.commit_group;" ::: "memory");
    }

    // epilogue: scale and store fp32
    float cs = scale[0] * iscale[0];
    int r0 = lid >> 2, c0 = (lid & 3) * 2;
#pragma unroll
    for (int mt = 0; mt < 4; ++mt) {
        size_t row0 = (size_t)tm * BM + wm * 64 + mt * 16 + r0;
#pragma unroll
        for (int nt = 0; nt < 8; ++nt) {
            size_t col = (size_t)tn * BN + wn * 64 + nt * 8 + c0;
            float2 v0, v1;
            v0.x = acc[mt][nt][0] * cs;
            v0.y = acc[mt][nt][1] * cs;
            v1.x = acc[mt][nt][2] * cs;
            v1.y = acc[mt][nt][3] * cs;
            *reinterpret_cast<float2*>(out + row0 * NN + col) = v0;
            *reinterpret_cast<float2*>(out + (row0 + 8) * NN + col) = v1;
        }
    }
}

// ---------------------------------------------------------------------------
extern "C" void kernel_launch(void* const* d_in, const int* in_sizes, int n_in,
                              void* d_out, int out_size) {
    const float* x      = (const float*)d_in[0];
    const int*   w      = (const int*)d_in[1];
    const float* scale  = (const float*)d_in[2];
    const float* iscale = (const float*)d_in[3];
    float* out = (float*)d_out;

    cudaFuncSetAttribute(gemm_kernel, cudaFuncAttributeMaxDynamicSharedMemorySize,
                         SMEM_TOTAL);

    quant_x_kernel<<<(MM * KK / 4) / 256, 256>>>(x, iscale);
    conv_w_kernel<<<(NN * KK / 4) / 256, 256>>>(w);
    gemm_kernel<<<(MM / BM) * (NN / BN), 256, SMEM_TOTAL>>>(out, scale, iscale);
}

// round 4
// speedup vs baseline: 2.4287x; 1.0087x over previous
#include <cuda_runtime.h>
#include <cuda_bf16.h>
#include <cstdint>

// Problem shape (fixed by the dataset)
#define MM 8192
#define NN 4096
#define KK 4096

// GEMM tiling (bf16 operands)
#define BM 256
#define BN 128
#define BK 64               // bf16 elems = 128 bytes = one swizzled row
#define STAGES 4
#define NKT (KK / BK)       // 64
#define A_TILE_BYTES (BM * 128)          // 32768
#define B_TILE_BYTES (BN * 128)          // 16384
#define STAGE_BYTES (A_TILE_BYTES + B_TILE_BYTES)   // 49152
#define SMEM_TOTAL (STAGES * STAGE_BYTES)           // 196608

// Scratch: quantized activations + bf16 weights (static device arrays allowed)
__device__ __align__(16) __nv_bfloat16 g_xq[(size_t)MM * KK];
__device__ __align__(16) __nv_bfloat16 g_wb[(size_t)NN * KK];

__device__ __forceinline__ uint32_t s2u(const void* p) {
    return (uint32_t)__cvta_generic_to_shared(p);
}

// XOR swizzle: 16B-chunk index (0..7) XOR (row & 7) -> conflict-free ldmatrix
__device__ __forceinline__ uint32_t tile_addr(uint32_t base, int row, int chunk) {
    return base + row * 128 + (((uint32_t)(chunk ^ (row & 7))) << 4);
}

__device__ __forceinline__ void ldsm_x4(uint32_t& r0, uint32_t& r1,
                                        uint32_t& r2, uint32_t& r3, uint32_t a) {
    asm volatile(
        "ldmatrix.sync.aligned.m8n8.x4.shared.b16 {%0,%1,%2,%3}, [%4];"
        : "=r"(r0), "=r"(r1), "=r"(r2), "=r"(r3) : "r"(a));
}

__device__ __forceinline__ void hmma(float* c, uint32_t a0, uint32_t a1, uint32_t a2,
                                     uint32_t a3, uint32_t b0, uint32_t b1) {
    asm volatile(
        "mma.sync.aligned.m16n8k16.row.col.f32.bf16.bf16.f32 "
        "{%0,%1,%2,%3}, {%4,%5,%6,%7}, {%8,%9}, {%0,%1,%2,%3};"
        : "+f"(c[0]), "+f"(c[1]), "+f"(c[2]), "+f"(c[3])
        : "r"(a0), "r"(a1), "r"(a2), "r"(a3), "r"(b0), "r"(b1));
}

// ---------------------------------------------------------------------------
// Kernel 1: quantize activations  x -> bf16(clip(round(x / s_in)))  (exact ints)
// ---------------------------------------------------------------------------
__global__ void quant_x_kernel(const float* __restrict__ x,
                               const float* __restrict__ iscale) {
    int i = blockIdx.x * blockDim.x + threadIdx.x;
    float inv = 1.0f / iscale[0];
    float4 v = reinterpret_cast<const float4*>(x)[i];
    float a0 = fminf(fmaxf(rintf(v.x * inv), -128.0f), 127.0f);
    float a1 = fminf(fmaxf(rintf(v.y * inv), -128.0f), 127.0f);
    float a2 = fminf(fmaxf(rintf(v.z * inv), -128.0f), 127.0f);
    float a3 = fminf(fmaxf(rintf(v.w * inv), -128.0f), 127.0f);
    __nv_bfloat162* o = reinterpret_cast<__nv_bfloat162*>(g_xq) + (size_t)i * 2;
    o[0] = __floats2bfloat162_rn(a0, a1);
    o[1] = __floats2bfloat162_rn(a2, a3);
}

// ---------------------------------------------------------------------------
// Kernel 2: weight int32 (int8 range) -> bf16 (exact)
// ---------------------------------------------------------------------------
__global__ void conv_w_kernel(const int* __restrict__ w) {
    int i = blockIdx.x * blockDim.x + threadIdx.x;
    int4 v = reinterpret_cast<const int4*>(w)[i];
    __nv_bfloat162* o = reinterpret_cast<__nv_bfloat162*>(g_wb) + (size_t)i * 2;
    o[0] = __floats2bfloat162_rn((float)v.x, (float)v.y);
    o[1] = __floats2bfloat162_rn((float)v.z, (float)v.w);
}

// ---------------------------------------------------------------------------
// Kernel 3: bf16 HMMA GEMM  out[m,n] = (sum_k A[m,k]*W[n,k]) * cs
// 256 threads = 8 warps in a 4x2 grid of 64x64 warp tiles.
// ---------------------------------------------------------------------------
__device__ __forceinline__ void load_stage(uint32_t sa, uint32_t sbw,
                                           const __nv_bfloat16* ak,
                                           const __nv_bfloat16* bk, int tid) {
    // 3072 16B chunks (A: 2048, B: 1024), 12 per thread, chunk-fastest coalesced
#pragma unroll
    for (int i = 0; i < 12; ++i) {
        int c = i * 256 + tid;
        int ch = c & 7;
        uint32_t dst;
        const __nv_bfloat16* g;
        if (c < 2048) {
            int row = c >> 3;
            dst = tile_addr(sa, row, ch);
            g = ak + (size_t)row * KK + ch * 8;
        } else {
            int row = (c - 2048) >> 3;
            dst = tile_addr(sbw, row, ch);
            g = bk + (size_t)row * KK + ch * 8;
        }
        asm volatile("cp.async.cg.shared.global [%0], [%1], 16;"
                     :: "r"(dst), "l"(g) : "memory");
    }
}

__device__ __forceinline__ void frag_load(uint32_t sa, uint32_t sbw, uint32_t chsh,
                                          const uint32_t* aoff, const uint32_t* axor,
                                          const uint32_t* boff, const uint32_t* bxor,
                                          uint32_t fa[4][4], uint32_t fb[4][4]) {
#pragma unroll
    for (int mt = 0; mt < 4; ++mt)
        ldsm_x4(fa[mt][0], fa[mt][1], fa[mt][2], fa[mt][3],
                sa + aoff[mt] + (chsh ^ axor[mt]));
#pragma unroll
    for (int p = 0; p < 4; ++p)
        ldsm_x4(fb[p][0], fb[p][1], fb[p][2], fb[p][3],
                sbw + boff[p] + (chsh ^ bxor[p]));
}

__global__ void __launch_bounds__(256, 1)
gemm_kernel(float* __restrict__ out,
            const float* __restrict__ scale, const float* __restrict__ iscale) {
    extern __shared__ char smem[];
    uint32_t sb = s2u(smem);
    int tid = threadIdx.x;
    int wid = tid >> 5, lid = tid & 31;
    int wm = wid >> 1, wn = wid & 1;          // 4x2 warps, 64x64 each

    int tm = blockIdx.x & (MM / BM - 1);      // m fast -> ktile slices stay in L2
    int tn = blockIdx.x >> 5;                 // MM/BM = 32

    const __nv_bfloat16* A  = g_xq + (size_t)tm * BM * KK;
    const __nv_bfloat16* Bw = g_wb + (size_t)tn * BN * KK;

    float acc[4][8][4];
#pragma unroll
    for (int i = 0; i < 4; ++i)
#pragma unroll
        for (int j = 0; j < 8; ++j)
#pragma unroll
            for (int k = 0; k < 4; ++k) acc[i][j][k] = 0.0f;

    // per-lane LDSM base offsets (row*128) and swizzle XOR terms ((row&7)<<4)
    int lrow = lid & 15;                 // row within 16-row block
    uint32_t lhish = (uint32_t)(lid >> 4) << 4;  // chunk low bit, pre-shifted
    uint32_t aoff[4], axor[4], boff[4], bxor[4];
#pragma unroll
    for (int mt = 0; mt < 4; ++mt) {
        int row = wm * 64 + mt * 16 + lrow;
        aoff[mt] = (uint32_t)row * 128;
        axor[mt] = (uint32_t)(row & 7) << 4;
    }
#pragma unroll
    for (int p = 0; p < 4; ++p) {
        int row = wn * 64 + p * 16 + lrow;
        boff[p] = (uint32_t)row * 128;
        bxor[p] = (uint32_t)(row & 7) << 4;
    }

    // prologue: fill STAGES-1 stages
#pragma unroll
    for (int s = 0; s < STAGES - 1; ++s) {
        load_stage(sb + s * STAGE_BYTES, sb + s * STAGE_BYTES + A_TILE_BYTES,
                   A + (size_t)s * BK, Bw + (size_t)s * BK, tid);
        asm volatile("cp.async.commit_group;" ::: "memory");
    }

    for (int kt = 0; kt < NKT; ++kt) {
        uint32_t st = sb + (kt % STAGES) * STAGE_BYTES;
        uint32_t sa = st, sbw = st + A_TILE_BYTES;
        asm volatile("cp.async.wait_group %0;" :: "n"(STAGES - 2) : "memory");
        __syncthreads();   // all chunks of stage kt arrived; stage kt-1 fully consumed

        // issue next tile's loads FIRST (into the stage consumed at kt-1)
        int ktn = kt + STAGES - 1;
        if (ktn < NKT) {
            uint32_t st2 = sb + (ktn % STAGES) * STAGE_BYTES;
            load_stage(st2, st2 + A_TILE_BYTES,
                       A + (size_t)ktn * BK, Bw + (size_t)ktn * BK, tid);
        }
        asm volatile("cp.async.commit_group;" ::: "memory");

        // compute with register double-buffered fragments
        uint32_t fa[2][4][4], fb[2][4][4];
        frag_load(sa, sbw, lhish, aoff, axor, boff, bxor, fa[0], fb[0]);
#pragma unroll
        for (int j = 0; j < 4; ++j) {          // 4 k-steps of 16
            int cur = j & 1, nxt = cur ^ 1;
            if (j < 3)
                frag_load(sa, sbw, ((uint32_t)(2 * (j + 1)) << 4) ^ lhish,
                          aoff, axor, boff, bxor, fa[nxt], fb[nxt]);
#pragma unroll
            for (int mt = 0; mt < 4; ++mt)
#pragma unroll
                for (int p = 0; p < 4; ++p) {
                    hmma(acc[mt][2 * p],     fa[cur][mt][0], fa[cur][mt][1],
                         fa[cur][mt][2], fa[cur][mt][3],
                         fb[cur][p][0], fb[cur][p][2]);
                    hmma(acc[mt][2 * p + 1], fa[cur][mt][0], fa[cur][mt][1],
                         fa[cur][mt][2], fa[cur][mt][3],
                         fb[cur][p][1], fb[cur][p][3]);
                }
        }
    }

    // epilogue: scale and store fp32
    float cs = scale[0] * iscale[0];
    int r0 = lid >> 2, c0 = (lid & 3) * 2;
#pragma unroll
    for (int mt = 0; mt < 4; ++mt) {
        size_t row0 = (size_t)tm * BM + wm * 64 + mt * 16 + r0;
#pragma unroll
        for (int nt = 0; nt < 8; ++nt) {
            size_t col = (size_t)tn * BN + wn * 64 + nt * 8 + c0;
            float2 v0, v1;
            v0.x = acc[mt][nt][0] * cs;
            v0.y = acc[mt][nt][1] * cs;
            v1.x = acc[mt][nt][2] * cs;
            v1.y = acc[mt][nt][3] * cs;
            *reinterpret_cast<float2*>(out + row0 * NN + col) = v0;
            *reinterpret_cast<float2*>(out + (row0 + 8) * NN + col) = v1;
        }
    }
}

// ---------------------------------------------------------------------------
extern "C" void kernel_launch(void* const* d_in, const int* in_sizes, int n_in,
                              void* d_out, int out_size) {
    const float* x      = (const float*)d_in[0];
    const int*   w      = (const int*)d_in[1];
    const float* scale  = (const float*)d_in[2];
    const float* iscale = (const float*)d_in[3];
    float* out = (float*)d_out;

    cudaFuncSetAttribute(gemm_kernel, cudaFuncAttributeMaxDynamicSharedMemorySize,
                         SMEM_TOTAL);

    quant_x_kernel<<<(MM * KK / 4) / 256, 256>>>(x, iscale);
    conv_w_kernel<<<(NN * KK / 4) / 256, 256>>>(w);
    gemm_kernel<<<(MM / BM) * (NN / BN), 256, SMEM_TOTAL>>>(out, scale, iscale);
}

// round 5
// speedup vs baseline: 2.4569x; 1.0116x over previous
#include <cuda_runtime.h>
#include <cuda_bf16.h>
#include <cstdint>

// Problem shape (fixed by the dataset)
#define MM 8192
#define NN 4096
#define KK 4096

// GEMM tiling (bf16 operands)
#define BM 128
#define BN 128
#define BK 64               // bf16 elems = 128 bytes = one swizzled row
#define STAGES 3
#define NKT (KK / BK)       // 64
#define A_TILE_BYTES (BM * 128)          // 16384
#define B_TILE_BYTES (BN * 128)          // 16384
#define STAGE_BYTES (A_TILE_BYTES + B_TILE_BYTES)   // 32768
#define SMEM_TOTAL (STAGES * STAGE_BYTES)           // 98304 -> 2 CTAs/SM

// Scratch: quantized activations + bf16 weights (static device arrays allowed)
__device__ __align__(16) __nv_bfloat16 g_xq[(size_t)MM * KK];
__device__ __align__(16) __nv_bfloat16 g_wb[(size_t)NN * KK];

__device__ __forceinline__ uint32_t s2u(const void* p) {
    return (uint32_t)__cvta_generic_to_shared(p);
}

// XOR swizzle: 16B-chunk index (0..7) XOR (row & 7) -> conflict-free ldmatrix
__device__ __forceinline__ uint32_t tile_addr(uint32_t base, int row, int chunk) {
    return base + row * 128 + (((uint32_t)(chunk ^ (row & 7))) << 4);
}

__device__ __forceinline__ void ldsm_x4(uint32_t& r0, uint32_t& r1,
                                        uint32_t& r2, uint32_t& r3, uint32_t a) {
    asm volatile(
        "ldmatrix.sync.aligned.m8n8.x4.shared.b16 {%0,%1,%2,%3}, [%4];"
        : "=r"(r0), "=r"(r1), "=r"(r2), "=r"(r3) : "r"(a));
}

__device__ __forceinline__ void hmma(float* c, uint32_t a0, uint32_t a1, uint32_t a2,
                                     uint32_t a3, uint32_t b0, uint32_t b1) {
    asm volatile(
        "mma.sync.aligned.m16n8k16.row.col.f32.bf16.bf16.f32 "
        "{%0,%1,%2,%3}, {%4,%5,%6,%7}, {%8,%9}, {%0,%1,%2,%3};"
        : "+f"(c[0]), "+f"(c[1]), "+f"(c[2]), "+f"(c[3])
        : "r"(a0), "r"(a1), "r"(a2), "r"(a3), "r"(b0), "r"(b1));
}

// ---------------------------------------------------------------------------
// Kernel 1: quantize activations  x -> bf16(clip(round(x / s_in)))  (exact ints)
// ---------------------------------------------------------------------------
__global__ void quant_x_kernel(const float* __restrict__ x,
                               const float* __restrict__ iscale) {
    int i = blockIdx.x * blockDim.x + threadIdx.x;
    float inv = 1.0f / iscale[0];
    float4 v = reinterpret_cast<const float4*>(x)[i];
    float a0 = fminf(fmaxf(rintf(v.x * inv), -128.0f), 127.0f);
    float a1 = fminf(fmaxf(rintf(v.y * inv), -128.0f), 127.0f);
    float a2 = fminf(fmaxf(rintf(v.z * inv), -128.0f), 127.0f);
    float a3 = fminf(fmaxf(rintf(v.w * inv), -128.0f), 127.0f);
    __nv_bfloat162* o = reinterpret_cast<__nv_bfloat162*>(g_xq) + (size_t)i * 2;
    o[0] = __floats2bfloat162_rn(a0, a1);
    o[1] = __floats2bfloat162_rn(a2, a3);
}

// ---------------------------------------------------------------------------
// Kernel 2: weight int32 (int8 range) -> bf16 (exact)
// ---------------------------------------------------------------------------
__global__ void conv_w_kernel(const int* __restrict__ w) {
    int i = blockIdx.x * blockDim.x + threadIdx.x;
    int4 v = reinterpret_cast<const int4*>(w)[i];
    __nv_bfloat162* o = reinterpret_cast<__nv_bfloat162*>(g_wb) + (size_t)i * 2;
    o[0] = __floats2bfloat162_rn((float)v.x, (float)v.y);
    o[1] = __floats2bfloat162_rn((float)v.z, (float)v.w);
}

// ---------------------------------------------------------------------------
// Kernel 3: bf16 HMMA GEMM  out[m,n] = (sum_k A[m,k]*W[n,k]) * cs
// 256 threads = 8 warps in a 2x4 grid of 64x32 warp tiles; 2 CTAs/SM.
// ---------------------------------------------------------------------------
__device__ __forceinline__ void load_stage(uint32_t sa, uint32_t sbw,
                                           const __nv_bfloat16* ak,
                                           const __nv_bfloat16* bk, int tid) {
    // 2048 16B chunks (A: 1024, B: 1024), 8 per thread, chunk-fastest coalesced
#pragma unroll
    for (int i = 0; i < 8; ++i) {
        int c = i * 256 + tid;
        int ch = c & 7;
        int row = (c >> 3) & 127;
        uint32_t dst;
        const __nv_bfloat16* g;
        if (c < 1024) {
            dst = tile_addr(sa, row, ch);
            g = ak + (size_t)row * KK + ch * 8;
        } else {
            dst = tile_addr(sbw, row, ch);
            g = bk + (size_t)row * KK + ch * 8;
        }
        asm volatile("cp.async.cg.shared.global [%0], [%1], 16;"
                     :: "r"(dst), "l"(g) : "memory");
    }
}

__global__ void __launch_bounds__(256, 2)
gemm_kernel(float* __restrict__ out,
            const float* __restrict__ scale, const float* __restrict__ iscale) {
    extern __shared__ char smem[];
    uint32_t sb = s2u(smem);
    int tid = threadIdx.x;
    int wid = tid >> 5, lid = tid & 31;
    int wm = wid >> 2, wn = wid & 3;          // 2x4 warps, 64x32 each

    int tm = blockIdx.x & (MM / BM - 1);      // m fast -> ktile slices stay in L2
    int tn = blockIdx.x >> 6;                 // MM/BM = 64

    const __nv_bfloat16* A  = g_xq + (size_t)tm * BM * KK;
    const __nv_bfloat16* Bw = g_wb + (size_t)tn * BN * KK;

    float acc[4][4][4];                        // [m16][n8][frag] = 64 regs
#pragma unroll
    for (int i = 0; i < 4; ++i)
#pragma unroll
        for (int j = 0; j < 4; ++j)
#pragma unroll
            for (int k = 0; k < 4; ++k) acc[i][j][k] = 0.0f;

    // per-lane LDSM base offsets (row*128) and swizzle XOR terms ((row&7)<<4)
    int lrow = lid & 15;                       // row within 16-row block
    uint32_t lhish = (uint32_t)(lid >> 4) << 4;
    uint32_t aoff[4], axor[4], boff[2], bxor[2];
#pragma unroll
    for (int mt = 0; mt < 4; ++mt) {
        int row = wm * 64 + mt * 16 + lrow;
        aoff[mt] = (uint32_t)row * 128;
        axor[mt] = (uint32_t)(row & 7) << 4;
    }
#pragma unroll
    for (int p = 0; p < 2; ++p) {
        int row = wn * 32 + p * 16 + lrow;
        boff[p] = (uint32_t)row * 128;
        bxor[p] = (uint32_t)(row & 7) << 4;
    }

    // prologue: fill STAGES-1 stages
#pragma unroll
    for (int s = 0; s < STAGES - 1; ++s) {
        load_stage(sb + s * STAGE_BYTES, sb + s * STAGE_BYTES + A_TILE_BYTES,
                   A + (size_t)s * BK, Bw + (size_t)s * BK, tid);
        asm volatile("cp.async.commit_group;" ::: "memory");
    }

    for (int kt = 0; kt < NKT; ++kt) {
        uint32_t st = sb + (kt % STAGES) * STAGE_BYTES;
        uint32_t sa = st, sbw = st + A_TILE_BYTES;
        asm volatile("cp.async.wait_group %0;" :: "n"(STAGES - 2) : "memory");
        __syncthreads();   // stage kt arrived; stage kt-1 fully consumed by all warps

        // issue next tile's loads FIRST (into the stage consumed at kt-1)
        int ktn = kt + STAGES - 1;
        if (ktn < NKT) {
            uint32_t st2 = sb + (ktn % STAGES) * STAGE_BYTES;
            load_stage(st2, st2 + A_TILE_BYTES,
                       A + (size_t)ktn * BK, Bw + (size_t)ktn * BK, tid);
        }
        asm volatile("cp.async.commit_group;" ::: "memory");

#pragma unroll
        for (int j = 0; j < 4; ++j) {          // 4 k-steps of 16
            uint32_t chsh = ((uint32_t)(2 * j) << 4) ^ lhish;
            uint32_t fa[4][4], fb[2][4];
#pragma unroll
            for (int mt = 0; mt < 4; ++mt)
                ldsm_x4(fa[mt][0], fa[mt][1], fa[mt][2], fa[mt][3],
                        sa + aoff[mt] + (chsh ^ axor[mt]));
#pragma unroll
            for (int p = 0; p < 2; ++p)
                ldsm_x4(fb[p][0], fb[p][1], fb[p][2], fb[p][3],
                        sbw + boff[p] + (chsh ^ bxor[p]));
#pragma unroll
            for (int mt = 0; mt < 4; ++mt)
#pragma unroll
                for (int p = 0; p < 2; ++p) {
                    hmma(acc[mt][2 * p],     fa[mt][0], fa[mt][1], fa[mt][2],
                         fa[mt][3], fb[p][0], fb[p][2]);
                    hmma(acc[mt][2 * p + 1], fa[mt][0], fa[mt][1], fa[mt][2],
                         fa[mt][3], fb[p][1], fb[p][3]);
                }
        }
    }

    // epilogue: scale and store fp32
    float cs = scale[0] * iscale[0];
    int r0 = lid >> 2, c0 = (lid & 3) * 2;
#pragma unroll
    for (int mt = 0; mt < 4; ++mt) {
        size_t row0 = (size_t)tm * BM + wm * 64 + mt * 16 + r0;
#pragma unroll
        for (int nt = 0; nt < 4; ++nt) {
            size_t col = (size_t)tn * BN + wn * 32 + nt * 8 + c0;
            float2 v0, v1;
            v0.x = acc[mt][nt][0] * cs;
            v0.y = acc[mt][nt][1] * cs;
            v1.x = acc[mt][nt][2] * cs;
            v1.y = acc[mt][nt][3] * cs;
            *reinterpret_cast<float2*>(out + row0 * NN + col) = v0;
            *reinterpret_cast<float2*>(out + (row0 + 8) * NN + col) = v1;
        }
    }
}

// ---------------------------------------------------------------------------
extern "C" void kernel_launch(void* const* d_in, const int* in_sizes, int n_in,
                              void* d_out, int out_size) {
    const float* x      = (const float*)d_in[0];
    const int*   w      = (const int*)d_in[1];
    const float* scale  = (const float*)d_in[2];
    const float* iscale = (const float*)d_in[3];
    float* out = (float*)d_out;

    cudaFuncSetAttribute(gemm_kernel, cudaFuncAttributeMaxDynamicSharedMemorySize,
                         SMEM_TOTAL);

    quant_x_kernel<<<(MM * KK / 4) / 256, 256>>>(x, iscale);
    conv_w_kernel<<<(NN * KK / 4) / 256, 256>>>(w);
    gemm_kernel<<<(MM / BM) * (NN / BN), 256, SMEM_TOTAL>>>(out, scale, iscale);
}